// round 8
// baseline (speedup 1.0000x reference)
#include <cuda_runtime.h>
#include <math.h>

constexpr int B = 16, C = 80, H = 64, W = 64, K = 20;
constexpr int HW = H * W;          // 4096
constexpr int NPAIR = B * K;       // 320
constexpr float PEAK_TEMP = 10.0f;

__device__ float g_partial[NPAIR];
__device__ unsigned int g_done = 0;   // completion counter (reset by last block)

// One block per (b,k) pair; the LAST block to finish also does the final sum.
__global__ __launch_bounds__(256) void fused_kernel(
    const float* __restrict__ cam,         // [B,C,H,W]
    const float* __restrict__ pred_boxes,  // [B,C,H,W,4]
    const float* __restrict__ gt_boxes,    // [B,K,4]
    const int*   __restrict__ gt_labels,   // [B,K]
    const float* __restrict__ threshold,   // [1]
    float* __restrict__ out, int out_size)
{
    const int pair = blockIdx.x;
    const int b    = pair / K;
    const int lab  = gt_labels[pair];
    const int t    = threadIdx.x;

    const float4 g = reinterpret_cast<const float4*>(gt_boxes)[pair];
    const float gx1 = g.x, gy1 = g.y, gx2 = g.z, gy2 = g.w;

    // Rectangular mask bounds (floor + clamp, exactly as _box_masks)
    const int i_min = max(0,     (int)floorf(gy1 * (float)H));
    const int i_max = min(H - 1, (int)floorf(gy2 * (float)H));
    const int j_min = max(0,     (int)floorf(gx1 * (float)W));
    const int j_max = min(W - 1, (int)floorf(gx2 * (float)W));

    const float thr = threshold[0];
    const float* __restrict__ map = cam + ((size_t)(b * C + lab)) * HW;

    float s_tot = 0.f, s_in = 0.f;   // cam sums
    float p_tot = 0.f, p_in = 0.f;   // peak (sigmoid) sums
    float best = -INFINITY;
    int bestIdx = HW;

    #pragma unroll
    for (int it = 0; it < HW / (256 * 4); ++it) {   // 4 iterations
        const int q = t + it * 256;
        const float4 v4 = reinterpret_cast<const float4*>(map)[q];
        const int base = q * 4;
        const int i  = base >> 6;     // row (W = 64)
        const int j0 = base & 63;     // first col of quad
        const bool row_in = (i >= i_min) & (i <= i_max);
        const float vv[4] = {v4.x, v4.y, v4.z, v4.w};
        #pragma unroll
        for (int e = 0; e < 4; ++e) {
            const float val = vv[e];
            // fast sigmoid: MUFU.EX2 path; |rel err| ~2^-22, fine at 1e-3 tol
            const float pk = 1.0f / (1.0f + __expf((thr - val) * PEAK_TEMP));
            s_tot += val;
            p_tot += pk;
            const int j = j0 + e;
            if (row_in & (j >= j_min) & (j <= j_max)) {
                s_in += val;
                p_in += pk;
                // ascending per-thread order -> strict > keeps first occurrence
                if (val > best) { best = val; bestIdx = base + e; }
            }
        }
    }

    // ---- block reductions (256 = 2^8: full power-of-two trees) ----
    __shared__ float red[256];
    auto block_sum = [&](float v) -> float {
        red[t] = v; __syncthreads();
        #pragma unroll
        for (int s = 128; s > 0; s >>= 1) {
            if (t < s) red[t] += red[t + s];
            __syncthreads();
        }
        const float r = red[0]; __syncthreads();
        return r;
    };
    const float S_tot = block_sum(s_tot);
    const float S_in  = block_sum(s_in);
    const float P_tot = block_sum(p_tot);
    const float P_in  = block_sum(p_in);

    __shared__ float rv[256];
    __shared__ int   ri[256];
    rv[t] = best; ri[t] = bestIdx; __syncthreads();
    #pragma unroll
    for (int s = 128; s > 0; s >>= 1) {
        if (t < s) {
            const float ov = rv[t + s]; const int oi = ri[t + s];
            if (ov > rv[t] || (ov == rv[t] && oi < ri[t])) { rv[t] = ov; ri[t] = oi; }
        }
        __syncthreads();
    }

    __shared__ bool s_last;
    if (t == 0) {
        const int   cnt   = (i_max - i_min + 1) * (j_max - j_min + 1);
        const float cnt_f = (float)cnt;
        const float out_f = (float)(HW - cnt);

        const float v_in  = S_in / fmaxf(cnt_f, 1.0f);
        const float v_out = (S_tot - S_in) / fmaxf(out_f, 1.0f);
        const float term_cam = (cnt > 0 ? 1.0f - v_in : 0.0f) +
                               (cnt < HW ? v_out : 0.0f);

        const float pv_in  = P_in / fmaxf(cnt_f, 1.0f);
        const float pv_out = (P_tot - P_in) / fmaxf(out_f, 1.0f);
        const float term_peak = (cnt > 0 ? 1.0f - pv_in : 0.0f) +
                                (cnt < HW ? pv_out : 0.0f);

        // Gather predicted box at argmax location
        const int bi = ri[0];
        const float* pb = pred_boxes + (((size_t)(b * C + lab)) * HW + bi) * 4;
        const float px1 = pb[0], py1 = pb[1], px2 = pb[2], py2 = pb[3];

        const float l1 = fabsf(px1 - gx1) + fabsf(py1 - gy1) +
                         fabsf(px2 - gx2) + fabsf(py2 - gy2);

        // GIoU
        const float ltx = fmaxf(px1, gx1), lty = fmaxf(py1, gy1);
        const float rbx = fminf(px2, gx2), rby = fminf(py2, gy2);
        const float iw  = fmaxf(rbx - ltx, 0.0f), ih = fmaxf(rby - lty, 0.0f);
        const float inter = iw * ih;
        const float ap = (px2 - px1) * (py2 - py1);
        const float ag = (gx2 - gx1) * (gy2 - gy1);
        const float uni = ap + ag - inter;
        const float iou = inter / uni;
        const float cx1 = fminf(px1, gx1), cy1 = fminf(py1, gy1);
        const float cx2 = fmaxf(px2, gx2), cy2 = fmaxf(py2, gy2);
        const float cw = fmaxf(cx2 - cx1, 0.0f), ch = fmaxf(cy2 - cy1, 0.0f);
        const float ac = cw * ch;
        const float giou = iou - (ac - uni) / ac;

        const float inv = 1.0f / (float)NPAIR;
        g_partial[pair] = (l1 * 0.25f +
                           2.0f * (1.0f - giou) +
                           0.5f * term_cam +
                           0.5f * term_peak) * inv;

        // Publish partial, then count completion.
        __threadfence();
        const unsigned int prev = atomicAdd(&g_done, 1u);
        s_last = (prev == (unsigned int)(NPAIR - 1));
    }
    __syncthreads();

    // ---- last block: deterministic 320-way final sum ----
    if (s_last) {
        // Each thread folds up to 2 partials (t and t+256), then 256-tree.
        float v = (t < NPAIR) ? g_partial[t] : 0.0f;
        const int t2 = t + 256;
        if (t2 < NPAIR) v += g_partial[t2];
        red[t] = v; __syncthreads();
        #pragma unroll
        for (int s = 128; s > 0; s >>= 1) {
            if (t < s) red[t] += red[t + s];
            __syncthreads();
        }
        if (t == 0) g_done = 0;                 // reset for next graph replay
        for (int i = t; i < out_size; i += 256) out[i] = red[0];
    }
}

extern "C" void kernel_launch(void* const* d_in, const int* in_sizes, int n_in,
                              void* d_out, int out_size)
{
    // Bind by element count (all five distinct)
    const float* cam        = nullptr;
    const float* pred_boxes = nullptr;
    const float* gt_boxes   = nullptr;
    const int*   gt_labels  = nullptr;
    const float* threshold  = nullptr;

    for (int i = 0; i < n_in; ++i) {
        switch (in_sizes[i]) {
            case B * C * H * W:       cam        = (const float*)d_in[i]; break;
            case B * C * H * W * 4:   pred_boxes = (const float*)d_in[i]; break;
            case B * K * 4:           gt_boxes   = (const float*)d_in[i]; break;
            case B * K:               gt_labels  = (const int*)d_in[i];   break;
            case 1:                   threshold  = (const float*)d_in[i]; break;
            default: break;
        }
    }

    fused_kernel<<<NPAIR, 256>>>(cam, pred_boxes, gt_boxes, gt_labels, threshold,
                                 (float*)d_out, out_size);
}

// round 9
// speedup vs baseline: 1.2340x; 1.2340x over previous
#include <cuda_runtime.h>
#include <math.h>

constexpr int B = 16, C = 80, H = 64, W = 64, K = 20;
constexpr int HW = H * W;          // 4096
constexpr int NPAIR = B * K;       // 320
constexpr float PEAK_TEMP = 10.0f;

__device__ float g_partial[NPAIR];
__device__ unsigned int g_done = 0;   // completion counter (reset by last block)

__device__ __forceinline__ float warp_sum(float v) {
    #pragma unroll
    for (int off = 16; off > 0; off >>= 1)
        v += __shfl_down_sync(0xFFFFFFFFu, v, off);
    return v;
}

// One block per (b,k) pair; LAST block to finish also does the final sum.
__global__ __launch_bounds__(256) void fused_kernel(
    const float* __restrict__ cam,         // [B,C,H,W]
    const float* __restrict__ pred_boxes,  // [B,C,H,W,4]
    const float* __restrict__ gt_boxes,    // [B,K,4]
    const int*   __restrict__ gt_labels,   // [B,K]
    const float* __restrict__ threshold,   // [1]
    float* __restrict__ out, int out_size)
{
    const int pair = blockIdx.x;
    const int b    = pair / K;
    const int lab  = gt_labels[pair];
    const int t    = threadIdx.x;
    const int wid  = t >> 5;
    const int lane = t & 31;

    const float4 g = reinterpret_cast<const float4*>(gt_boxes)[pair];
    const float gx1 = g.x, gy1 = g.y, gx2 = g.z, gy2 = g.w;

    const int i_min = max(0,     (int)floorf(gy1 * (float)H));
    const int i_max = min(H - 1, (int)floorf(gy2 * (float)H));
    const int j_min = max(0,     (int)floorf(gx1 * (float)W));
    const int j_max = min(W - 1, (int)floorf(gx2 * (float)W));

    const float thr = threshold[0];
    const float* __restrict__ map = cam + ((size_t)(b * C + lab)) * HW;

    // ---- front-batch ALL loads: 4 independent LDG.128 in flight (MLP=4) ----
    float4 v4[4];
    #pragma unroll
    for (int it = 0; it < 4; ++it)
        v4[it] = reinterpret_cast<const float4*>(map)[t + it * 256];

    float s_tot = 0.f, s_in = 0.f;
    float p_tot = 0.f, p_in = 0.f;
    float best = -INFINITY;
    int bestIdx = HW;

    #pragma unroll
    for (int it = 0; it < 4; ++it) {
        const int base = (t + it * 256) * 4;
        const int i  = base >> 6;      // row (W = 64)
        const int j0 = base & 63;
        const bool row_in = (i >= i_min) & (i <= i_max);
        const float vv[4] = {v4[it].x, v4[it].y, v4[it].z, v4[it].w};
        #pragma unroll
        for (int e = 0; e < 4; ++e) {
            const float val = vv[e];
            const float pk = 1.0f / (1.0f + __expf((thr - val) * PEAK_TEMP));
            s_tot += val;
            p_tot += pk;
            const int j = j0 + e;
            if (row_in & (j >= j_min) & (j <= j_max)) {
                s_in += val;
                p_in += pk;
                if (val > best) { best = val; bestIdx = base + e; }  // asc order -> first occurrence
            }
        }
    }

    // ---- warp-level reduction: 4 sums + argmax, concurrent (ILP), no barriers ----
    #pragma unroll
    for (int off = 16; off > 0; off >>= 1) {
        s_tot += __shfl_down_sync(0xFFFFFFFFu, s_tot, off);
        s_in  += __shfl_down_sync(0xFFFFFFFFu, s_in,  off);
        p_tot += __shfl_down_sync(0xFFFFFFFFu, p_tot, off);
        p_in  += __shfl_down_sync(0xFFFFFFFFu, p_in,  off);
        const float ov = __shfl_down_sync(0xFFFFFFFFu, best,    off);
        const int   oi = __shfl_down_sync(0xFFFFFFFFu, bestIdx, off);
        if (ov > best || (ov == best && oi < bestIdx)) { best = ov; bestIdx = oi; }
    }

    // ---- cross-warp combine (8 warps) via shared, one barrier ----
    __shared__ float sh_stot[8], sh_sin[8], sh_ptot[8], sh_pin[8];
    __shared__ float sh_bv[8];
    __shared__ int   sh_bi[8];
    if (lane == 0) {
        sh_stot[wid] = s_tot; sh_sin[wid] = s_in;
        sh_ptot[wid] = p_tot; sh_pin[wid] = p_in;
        sh_bv[wid] = best;    sh_bi[wid] = bestIdx;
    }
    __syncthreads();

    __shared__ bool s_last;
    if (wid == 0) {
        // lanes 0..7 hold warp results; lanes 8..31 identity
        float a_stot = (lane < 8) ? sh_stot[lane] : 0.f;
        float a_sin  = (lane < 8) ? sh_sin[lane]  : 0.f;
        float a_ptot = (lane < 8) ? sh_ptot[lane] : 0.f;
        float a_pin  = (lane < 8) ? sh_pin[lane]  : 0.f;
        float a_bv   = (lane < 8) ? sh_bv[lane]   : -INFINITY;
        int   a_bi   = (lane < 8) ? sh_bi[lane]   : HW;
        #pragma unroll
        for (int off = 4; off > 0; off >>= 1) {
            a_stot += __shfl_down_sync(0xFFFFFFFFu, a_stot, off);
            a_sin  += __shfl_down_sync(0xFFFFFFFFu, a_sin,  off);
            a_ptot += __shfl_down_sync(0xFFFFFFFFu, a_ptot, off);
            a_pin  += __shfl_down_sync(0xFFFFFFFFu, a_pin,  off);
            const float ov = __shfl_down_sync(0xFFFFFFFFu, a_bv, off);
            const int   oi = __shfl_down_sync(0xFFFFFFFFu, a_bi, off);
            if (ov > a_bv || (ov == a_bv && oi < a_bi)) { a_bv = ov; a_bi = oi; }
        }

        if (lane == 0) {
            const float S_tot = a_stot, S_in = a_sin;
            const float P_tot = a_ptot, P_in = a_pin;

            const int   cnt   = (i_max - i_min + 1) * (j_max - j_min + 1);
            const float cnt_f = (float)cnt;
            const float out_f = (float)(HW - cnt);

            const float v_in  = S_in / fmaxf(cnt_f, 1.0f);
            const float v_out = (S_tot - S_in) / fmaxf(out_f, 1.0f);
            const float term_cam = (cnt > 0 ? 1.0f - v_in : 0.0f) +
                                   (cnt < HW ? v_out : 0.0f);

            const float pv_in  = P_in / fmaxf(cnt_f, 1.0f);
            const float pv_out = (P_tot - P_in) / fmaxf(out_f, 1.0f);
            const float term_peak = (cnt > 0 ? 1.0f - pv_in : 0.0f) +
                                    (cnt < HW ? pv_out : 0.0f);

            const int bi = a_bi;
            const float* pb = pred_boxes + (((size_t)(b * C + lab)) * HW + bi) * 4;
            const float px1 = pb[0], py1 = pb[1], px2 = pb[2], py2 = pb[3];

            const float l1 = fabsf(px1 - gx1) + fabsf(py1 - gy1) +
                             fabsf(px2 - gx2) + fabsf(py2 - gy2);

            const float ltx = fmaxf(px1, gx1), lty = fmaxf(py1, gy1);
            const float rbx = fminf(px2, gx2), rby = fminf(py2, gy2);
            const float iw  = fmaxf(rbx - ltx, 0.0f), ih = fmaxf(rby - lty, 0.0f);
            const float inter = iw * ih;
            const float ap = (px2 - px1) * (py2 - py1);
            const float ag = (gx2 - gx1) * (gy2 - gy1);
            const float uni = ap + ag - inter;
            const float iou = inter / uni;
            const float cx1 = fminf(px1, gx1), cy1 = fminf(py1, gy1);
            const float cx2 = fmaxf(px2, gx2), cy2 = fmaxf(py2, gy2);
            const float cw = fmaxf(cx2 - cx1, 0.0f), ch = fmaxf(cy2 - cy1, 0.0f);
            const float ac = cw * ch;
            const float giou = iou - (ac - uni) / ac;

            const float inv = 1.0f / (float)NPAIR;
            g_partial[pair] = (l1 * 0.25f +
                               2.0f * (1.0f - giou) +
                               0.5f * term_cam +
                               0.5f * term_peak) * inv;

            __threadfence();
            const unsigned int prev = atomicAdd(&g_done, 1u);
            s_last = (prev == (unsigned int)(NPAIR - 1));
        }
    }
    __syncthreads();

    // ---- last block: deterministic 320-way final sum (shuffle-based) ----
    if (s_last) {
        float v = (t < NPAIR) ? g_partial[t] : 0.0f;
        if (t + 256 < NPAIR) v += g_partial[t + 256];
        v = warp_sum(v);
        __shared__ float sh_f[8];
        if (lane == 0) sh_f[wid] = v;
        __syncthreads();
        if (wid == 0) {
            float a = (lane < 8) ? sh_f[lane] : 0.f;
            #pragma unroll
            for (int off = 4; off > 0; off >>= 1)
                a += __shfl_down_sync(0xFFFFFFFFu, a, off);
            if (lane == 0) {
                g_done = 0;                       // reset for next replay
                sh_f[0] = a;
            }
        }
        __syncthreads();
        for (int i = t; i < out_size; i += 256) out[i] = sh_f[0];
    }
}

extern "C" void kernel_launch(void* const* d_in, const int* in_sizes, int n_in,
                              void* d_out, int out_size)
{
    const float* cam        = nullptr;
    const float* pred_boxes = nullptr;
    const float* gt_boxes   = nullptr;
    const int*   gt_labels  = nullptr;
    const float* threshold  = nullptr;

    for (int i = 0; i < n_in; ++i) {
        switch (in_sizes[i]) {
            case B * C * H * W:       cam        = (const float*)d_in[i]; break;
            case B * C * H * W * 4:   pred_boxes = (const float*)d_in[i]; break;
            case B * K * 4:           gt_boxes   = (const float*)d_in[i]; break;
            case B * K:               gt_labels  = (const int*)d_in[i];   break;
            case 1:                   threshold  = (const float*)d_in[i]; break;
            default: break;
        }
    }

    fused_kernel<<<NPAIR, 256>>>(cam, pred_boxes, gt_boxes, gt_labels, threshold,
                                 (float*)d_out, out_size);
}

// round 11
// speedup vs baseline: 1.2848x; 1.0411x over previous
#include <cuda_runtime.h>
#include <math.h>

constexpr int B = 16, C = 80, H = 64, W = 64, K = 20;
constexpr int HW = H * W;          // 4096
constexpr int NPAIR = B * K;       // 320
// PEAK_TEMP = 10: sigmoid(10*(v-thr)) = 0.5*tanh(5*(v-thr)) + 0.5

__device__ float g_partial[NPAIR];
__device__ unsigned int g_done = 0;   // completion counter (reset by last block)

__device__ __forceinline__ float tanh_fast(float x) {
    float y;
    asm("tanh.approx.f32 %0, %1;" : "=f"(y) : "f"(x));
    return y;
}

__device__ __forceinline__ float warp_sum(float v) {
    #pragma unroll
    for (int off = 16; off > 0; off >>= 1)
        v += __shfl_down_sync(0xFFFFFFFFu, v, off);
    return v;
}

// One block per (b,k) pair; LAST block to finish also does the final sum.
__global__ __launch_bounds__(256) void fused_kernel(
    const float* __restrict__ cam,         // [B,C,H,W]
    const float* __restrict__ pred_boxes,  // [B,C,H,W,4]
    const float* __restrict__ gt_boxes,    // [B,K,4]
    const int*   __restrict__ gt_labels,   // [B,K]
    const float* __restrict__ threshold,   // [1]
    float* __restrict__ out, int out_size)
{
    const int pair = blockIdx.x;
    const int b    = pair / K;
    const int lab  = __ldg(&gt_labels[pair]);   // first: unblocks the cam loads
    const int t    = threadIdx.x;
    const int wid  = t >> 5;
    const int lane = t & 31;

    const float* __restrict__ map = cam + ((size_t)(b * C + lab)) * HW;

    // ---- front-batch ALL cam loads: 4 independent LDG.128 in flight ----
    float4 v4[4];
    #pragma unroll
    for (int it = 0; it < 4; ++it)
        v4[it] = reinterpret_cast<const float4*>(map)[t + it * 256];

    const float4 g = reinterpret_cast<const float4*>(gt_boxes)[pair];
    const float gx1 = g.x, gy1 = g.y, gx2 = g.z, gy2 = g.w;

    const int i_min = max(0,     (int)floorf(gy1 * (float)H));
    const int i_max = min(H - 1, (int)floorf(gy2 * (float)H));
    const int j_min = max(0,     (int)floorf(gx1 * (float)W));
    const int j_max = min(W - 1, (int)floorf(gx2 * (float)W));

    const float thr5 = __ldg(&threshold[0]) * 5.0f;

    float s_tot = 0.f, s_in = 0.f;   // cam sums
    float q_tot = 0.f, q_in = 0.f;   // raw tanh sums (affine-fixed later)
    float best = -INFINITY;
    int bestIdx = HW;

    #pragma unroll
    for (int it = 0; it < 4; ++it) {
        const int base = (t + it * 256) * 4;
        const int i  = base >> 6;      // row (W = 64)
        const int j0 = base & 63;
        const bool row_in = (i >= i_min) & (i <= i_max);
        const float vv[4] = {v4[it].x, v4[it].y, v4[it].z, v4[it].w};
        #pragma unroll
        for (int e = 0; e < 4; ++e) {
            const float val = vv[e];
            // sigmoid(10*(val-thr)) = 0.5*tanh(5*val - 5*thr) + 0.5 ; 1 MUFU op
            const float th = tanh_fast(fmaf(val, 5.0f, -thr5));
            s_tot += val;
            q_tot += th;
            const int j = j0 + e;
            if (row_in & (j >= j_min) & (j <= j_max)) {
                s_in += val;
                q_in += th;
                if (val > best) { best = val; bestIdx = base + e; }  // asc order -> first occurrence
            }
        }
    }

    // ---- warp-level reduction: 4 sums + argmax, concurrent, no barriers ----
    #pragma unroll
    for (int off = 16; off > 0; off >>= 1) {
        s_tot += __shfl_down_sync(0xFFFFFFFFu, s_tot, off);
        s_in  += __shfl_down_sync(0xFFFFFFFFu, s_in,  off);
        q_tot += __shfl_down_sync(0xFFFFFFFFu, q_tot, off);
        q_in  += __shfl_down_sync(0xFFFFFFFFu, q_in,  off);
        const float ov = __shfl_down_sync(0xFFFFFFFFu, best,    off);
        const int   oi = __shfl_down_sync(0xFFFFFFFFu, bestIdx, off);
        if (ov > best || (ov == best && oi < bestIdx)) { best = ov; bestIdx = oi; }
    }

    // ---- cross-warp combine (8 warps) via shared, one barrier ----
    __shared__ float sh_stot[8], sh_sin[8], sh_qtot[8], sh_qin[8];
    __shared__ float sh_bv[8];
    __shared__ int   sh_bi[8];
    if (lane == 0) {
        sh_stot[wid] = s_tot; sh_sin[wid] = s_in;
        sh_qtot[wid] = q_tot; sh_qin[wid] = q_in;
        sh_bv[wid] = best;    sh_bi[wid] = bestIdx;
    }
    __syncthreads();

    __shared__ bool s_last;
    if (wid == 0) {
        float a_stot = (lane < 8) ? sh_stot[lane] : 0.f;
        float a_sin  = (lane < 8) ? sh_sin[lane]  : 0.f;
        float a_qtot = (lane < 8) ? sh_qtot[lane] : 0.f;
        float a_qin  = (lane < 8) ? sh_qin[lane]  : 0.f;
        float a_bv   = (lane < 8) ? sh_bv[lane]   : -INFINITY;
        int   a_bi   = (lane < 8) ? sh_bi[lane]   : HW;
        #pragma unroll
        for (int off = 4; off > 0; off >>= 1) {
            a_stot += __shfl_down_sync(0xFFFFFFFFu, a_stot, off);
            a_sin  += __shfl_down_sync(0xFFFFFFFFu, a_sin,  off);
            a_qtot += __shfl_down_sync(0xFFFFFFFFu, a_qtot, off);
            a_qin  += __shfl_down_sync(0xFFFFFFFFu, a_qin,  off);
            const float ov = __shfl_down_sync(0xFFFFFFFFu, a_bv, off);
            const int   oi = __shfl_down_sync(0xFFFFFFFFu, a_bi, off);
            if (ov > a_bv || (ov == a_bv && oi < a_bi)) { a_bv = ov; a_bi = oi; }
        }

        if (lane == 0) {
            const int   cnt   = (i_max - i_min + 1) * (j_max - j_min + 1);
            const float cnt_f = (float)cnt;
            const float out_f = (float)(HW - cnt);

            // Reconstruct sigmoid sums from tanh sums: P = 0.5*Q + 0.5*count
            const float P_tot = 0.5f * a_qtot + 0.5f * (float)HW;
            const float P_in  = 0.5f * a_qin  + 0.5f * cnt_f;

            const float v_in  = a_sin / fmaxf(cnt_f, 1.0f);
            const float v_out = (a_stot - a_sin) / fmaxf(out_f, 1.0f);
            const float term_cam = (cnt > 0 ? 1.0f - v_in : 0.0f) +
                                   (cnt < HW ? v_out : 0.0f);

            const float pv_in  = P_in / fmaxf(cnt_f, 1.0f);
            const float pv_out = (P_tot - P_in) / fmaxf(out_f, 1.0f);
            const float term_peak = (cnt > 0 ? 1.0f - pv_in : 0.0f) +
                                    (cnt < HW ? pv_out : 0.0f);

            // Gather predicted box at argmax location
            const float* pb = pred_boxes + (((size_t)(b * C + lab)) * HW + a_bi) * 4;
            const float px1 = pb[0], py1 = pb[1], px2 = pb[2], py2 = pb[3];

            const float l1 = fabsf(px1 - gx1) + fabsf(py1 - gy1) +
                             fabsf(px2 - gx2) + fabsf(py2 - gy2);

            const float ltx = fmaxf(px1, gx1), lty = fmaxf(py1, gy1);
            const float rbx = fminf(px2, gx2), rby = fminf(py2, gy2);
            const float iw  = fmaxf(rbx - ltx, 0.0f), ih = fmaxf(rby - lty, 0.0f);
            const float inter = iw * ih;
            const float ap = (px2 - px1) * (py2 - py1);
            const float ag = (gx2 - gx1) * (gy2 - gy1);
            const float uni = ap + ag - inter;
            const float iou = inter / uni;
            const float cx1 = fminf(px1, gx1), cy1 = fminf(py1, gy1);
            const float cx2 = fmaxf(px2, gx2), cy2 = fmaxf(py2, gy2);
            const float cw = fmaxf(cx2 - cx1, 0.0f), ch = fmaxf(cy2 - cy1, 0.0f);
            const float ac = cw * ch;
            const float giou = iou - (ac - uni) / ac;

            const float inv = 1.0f / (float)NPAIR;
            g_partial[pair] = (l1 * 0.25f +
                               2.0f * (1.0f - giou) +
                               0.5f * term_cam +
                               0.5f * term_peak) * inv;

            // Release-add on the counter orders the partial store before it;
            // acquire half synchronizes the last block. Replaces __threadfence().
            unsigned int prev;
            asm volatile("atom.acq_rel.gpu.global.add.u32 %0, [%1], 1;"
                         : "=r"(prev) : "l"(&g_done) : "memory");
            s_last = (prev == (unsigned int)(NPAIR - 1));
        }
    }
    __syncthreads();

    // ---- last block: deterministic 320-way final sum (shuffle-based) ----
    if (s_last) {
        float v = (t < NPAIR) ? g_partial[t] : 0.0f;
        if (t + 256 < NPAIR) v += g_partial[t + 256];
        v = warp_sum(v);
        __shared__ float sh_f[8];
        if (lane == 0) sh_f[wid] = v;
        __syncthreads();
        if (wid == 0) {
            float a = (lane < 8) ? sh_f[lane] : 0.f;
            #pragma unroll
            for (int off = 4; off > 0; off >>= 1)
                a += __shfl_down_sync(0xFFFFFFFFu, a, off);
            if (lane == 0) {
                g_done = 0;                       // reset for next replay
                sh_f[0] = a;
            }
        }
        __syncthreads();
        for (int i = t; i < out_size; i += 256) out[i] = sh_f[0];
    }
}

extern "C" void kernel_launch(void* const* d_in, const int* in_sizes, int n_in,
                              void* d_out, int out_size)
{
    const float* cam        = nullptr;
    const float* pred_boxes = nullptr;
    const float* gt_boxes   = nullptr;
    const int*   gt_labels  = nullptr;
    const float* threshold  = nullptr;

    for (int i = 0; i < n_in; ++i) {
        switch (in_sizes[i]) {
            case B * C * H * W:       cam        = (const float*)d_in[i]; break;
            case B * C * H * W * 4:   pred_boxes = (const float*)d_in[i]; break;
            case B * K * 4:           gt_boxes   = (const float*)d_in[i]; break;
            case B * K:               gt_labels  = (const int*)d_in[i];   break;
            case 1:                   threshold  = (const float*)d_in[i]; break;
            default: break;
        }
    }

    fused_kernel<<<NPAIR, 256>>>(cam, pred_boxes, gt_boxes, gt_labels, threshold,
                                 (float*)d_out, out_size);
}